// round 2
// baseline (speedup 1.0000x reference)
#include <cuda_runtime.h>
#include <cstdint>

// Scratch for inv_in: [comp][b][i][f], f in 0..255 (f<128: extract00; f>=128: trace)
__device__ float g_inv[2 * 32 * 8 * 256];

// Kernel 1: sparse gather. Two threads per (comp,b,i,c): h = which half of k.
// 2*32*8*128*2 = 131072 threads.
__global__ void __launch_bounds__(256) gather_kernel(
    const float* __restrict__ Hre,
    const float* __restrict__ Him,
    float* __restrict__ out)
{
    int g    = blockIdx.x * 256 + threadIdx.x;
    int h    = g & 1;            // k-half
    int c    = (g >> 1) & 127;
    int i    = (g >> 8) & 7;
    int b    = (g >> 11) & 31;
    int comp = (g >> 16) & 1;

    const float* __restrict__ H = comp ? Him : Hre;
    const float* __restrict__ base = H + ((size_t)((b << 7) + c) << 14);

    const int r0 = i << 4;       // block start row/col
    const int k0 = h << 3;       // 0 or 8

    // Column 0 of the block: H[r0+k0+k, r0], k=0..7 (stride 512 B)
    float col[8];
    #pragma unroll
    for (int k = 0; k < 8; k++)
        col[k] = __ldg(base + (size_t)(r0 + k0 + k) * 128 + r0);

    // Partial trace of diag of block[1:,1:]
    float tr = 0.0f;
    #pragma unroll
    for (int k = 0; k < 8; k++) {
        int kk = k0 + k;
        if (kk >= 1)
            tr += __ldg(base + (size_t)(r0 + kk) * 128 + (r0 + kk));
    }
    // partner thread (h^1) is adjacent lane
    tr += __shfl_xor_sync(0xffffffffu, tr, 1);

    // out shape (2,B,n,C,16): slots k0..k0+7 except slot 0 (filled by gemm).
    // Stores: each thread writes a contiguous 28-32B chunk; lanes tile 64B strides -> coalesced.
    float* __restrict__ ob =
        out + ((size_t)((((comp << 5) + b) * 8 + i) * 128 + c) << 4) + k0;
    #pragma unroll
    for (int l = 0; l < 8; l++)
        if (k0 + l >= 1) ob[l] = col[l];

    if (h == 0) {
        int gi = (((comp << 5) + b) * 8 + i) * 256;
        g_inv[gi + c]       = col[0];  // extract00
        g_inv[gi + 128 + c] = tr;      // full trace (after shfl)
    }
}

// Kernel 2: inv = inv_in @ W.T, write out[...,0].
// One block per (comp,b,i) = 512 blocks, 256 threads.
// Thread t: co = t&127, h = t>>7 -> half-dot of length 128, shared reduce.
__global__ void __launch_bounds__(256) gemm_kernel(
    const float* __restrict__ Wr,
    const float* __restrict__ Wi,
    float* __restrict__ out)
{
    int blk  = blockIdx.x;        // ((comp*32+b)*8+i)
    int comp = blk >> 8;
    const float* __restrict__ W = comp ? Wi : Wr;

    __shared__ float sh[256];
    __shared__ float part[256];

    int t = threadIdx.x;
    sh[t] = g_inv[blk * 256 + t];
    __syncthreads();

    int co = t & 127;
    int h  = t >> 7;
    const float* __restrict__ wrow = W + (size_t)co * 256 + h * 128;
    const float* __restrict__ srow = sh + h * 128;

    float acc0 = 0.0f, acc1 = 0.0f;
    #pragma unroll 8
    for (int f = 0; f < 128; f += 2) {
        acc0 += srow[f]     * __ldg(wrow + f);
        acc1 += srow[f + 1] * __ldg(wrow + f + 1);
    }
    part[t] = acc0 + acc1;
    __syncthreads();

    if (t < 128)
        out[(size_t)(blk * 128 + t) << 4] = part[t] + part[t + 128];
}

extern "C" void kernel_launch(void* const* d_in, const int* in_sizes, int n_in,
                              void* d_out, int out_size)
{
    const float* Hre = (const float*)d_in[0];
    const float* Him = (const float*)d_in[1];
    const float* Wr  = (const float*)d_in[2];
    const float* Wi  = (const float*)d_in[3];
    float* out = (float*)d_out;

    gather_kernel<<<512, 256>>>(Hre, Him, out);   // 131072 threads
    gemm_kernel<<<512, 256>>>(Wr, Wi, out);       // 512 blocks
}